// round 2
// baseline (speedup 1.0000x reference)
#include <cuda_runtime.h>
#include <math.h>

#define NB 4
#define TT 1024
#define DD 1024
#define HH 16
#define CC 64
// qkv: [4096, 3072]; q_rot/o: 16MB each
__device__ float g_qkv[(size_t)NB * TT * 3 * DD];
__device__ float g_q[(size_t)NB * HH * TT * CC];
__device__ float g_o[(size_t)NB * TT * DD];

// ---------------------------------------------------------------------------
// GEMM (TN): C[M,N] = A[M,K] @ B[N,K]^T   (A,B,C row-major, fp32)
// BM=BN=128, BK=16, 256 threads, 8x8 micro-tile per thread.
// ---------------------------------------------------------------------------
__global__ __launch_bounds__(256) void gemm_tn(const float* __restrict__ A,
                                               const float* __restrict__ B,
                                               float* __restrict__ C,
                                               int M, int N, int K) {
    constexpr int BM = 128, BN = 128, BK = 16;
    __shared__ float As[BK][BM];
    __shared__ float Bs[BK][BN];
    const int tid = threadIdx.x;
    const int tx = tid % 16, ty = tid / 16;
    const int m0 = blockIdx.y * BM, n0 = blockIdx.x * BN;
    const int lrow = tid / 4;         // 0..63
    const int lcol = (tid % 4) * 4;   // 0,4,8,12

    float acc[8][8] = {};

    for (int k0 = 0; k0 < K; k0 += BK) {
#pragma unroll
        for (int h = 0; h < 2; h++) {
            int r = lrow + h * 64;
            float4 v = *reinterpret_cast<const float4*>(
                &A[(size_t)(m0 + r) * K + k0 + lcol]);
            As[lcol + 0][r] = v.x; As[lcol + 1][r] = v.y;
            As[lcol + 2][r] = v.z; As[lcol + 3][r] = v.w;
        }
#pragma unroll
        for (int h = 0; h < 2; h++) {
            int r = lrow + h * 64;
            float4 v = *reinterpret_cast<const float4*>(
                &B[(size_t)(n0 + r) * K + k0 + lcol]);
            Bs[lcol + 0][r] = v.x; Bs[lcol + 1][r] = v.y;
            Bs[lcol + 2][r] = v.z; Bs[lcol + 3][r] = v.w;
        }
        __syncthreads();
#pragma unroll
        for (int kk = 0; kk < BK; kk++) {
            float ra[8], rb[8];
#pragma unroll
            for (int i = 0; i < 8; i++) ra[i] = As[kk][ty * 8 + i];
#pragma unroll
            for (int j = 0; j < 8; j++) rb[j] = Bs[kk][tx * 8 + j];
#pragma unroll
            for (int i = 0; i < 8; i++)
#pragma unroll
                for (int j = 0; j < 8; j++) acc[i][j] += ra[i] * rb[j];
        }
        __syncthreads();
    }
#pragma unroll
    for (int i = 0; i < 8; i++) {
        int m = m0 + ty * 8 + i;
#pragma unroll
        for (int j = 0; j < 8; j += 4) {
            float4 v = make_float4(acc[i][j], acc[i][j + 1], acc[i][j + 2],
                                   acc[i][j + 3]);
            *reinterpret_cast<float4*>(&C[(size_t)m * N + n0 + tx * 8 + j]) = v;
        }
    }
}

// ---------------------------------------------------------------------------
// RoPE + transpose. One thread per (n,t,h,j) pair; rotates q & k pairs,
// copies v. Writes q to g_q, k/v straight to the output buffer (both in
// [N,H,T,C] layout).
// ---------------------------------------------------------------------------
__global__ void rope_kernel(const float* __restrict__ r,
                            float* __restrict__ kout,
                            float* __restrict__ vout) {
    int idx = blockIdx.x * blockDim.x + threadIdx.x;
    const int TOT = NB * TT * HH * (CC / 2);
    if (idx >= TOT) return;
    int j = idx % (CC / 2);
    int h = (idx / (CC / 2)) % HH;
    int t = (idx / (CC / 2) / HH) % TT;
    int n = idx / (CC / 2) / HH / TT;
    size_t row = (size_t)n * TT + t;
    const float* p = &g_qkv[row * (3 * DD) + h * CC + 2 * j];
    float q0 = p[0], q1 = p[1];
    float k0 = p[DD], k1 = p[DD + 1];
    float v0 = p[2 * DD], v1 = p[2 * DD + 1];
    float ang = r[row * (CC / 2) + j];
    float cs = cosf(ang), sn = sinf(ang);
    size_t o = (((size_t)n * HH + h) * TT + t) * CC + 2 * j;
    g_q[o] = q0 * cs - q1 * sn;
    g_q[o + 1] = q0 * sn + q1 * cs;
    kout[o] = k0 * cs - k1 * sn;
    kout[o + 1] = k0 * sn + k1 * cs;
    vout[o] = v0;
    vout[o + 1] = v1;
}

// ---------------------------------------------------------------------------
// Flash-style attention. Block = (q-tile of 32, h, n). 256 threads (16x16).
// Each thread: 2x2 of the 32x32 S tile, 2x4 of the 32x64 O tile.
// Online softmax; row reductions via shfl over aligned 16-lane groups.
// Mask is int32 (harness materializes the bool tensor as int32).
// Writes O directly in [N, T, H*C] layout for the output GEMM.
// ---------------------------------------------------------------------------
__global__ __launch_bounds__(256) void attn_kernel(
    const float* __restrict__ Kg, const float* __restrict__ Vg,
    const int* __restrict__ mask) {
    constexpr int BQ = 32, BS = 32;
    __shared__ float Qs[BQ][CC];        // 8KB
    __shared__ float Ks[BS][CC + 4];    // padded (16B aligned rows)
    __shared__ float Vs[BS][CC + 4];
    __shared__ float Ps[BQ][BS + 1];

    const int n = blockIdx.z, h = blockIdx.y, q0 = blockIdx.x * BQ;
    const int tid = threadIdx.x;
    const int tx = tid % 16, ty = tid / 16;
    const size_t base = ((size_t)n * HH + h) * TT;

    {   // load Q tile (already rotated)
        int r = tid / 8;
        int c = (tid % 8) * 8;
        const float* src = &g_q[(base + q0 + r) * CC + c];
        *reinterpret_cast<float4*>(&Qs[r][c]) =
            *reinterpret_cast<const float4*>(src);
        *reinterpret_cast<float4*>(&Qs[r][c + 4]) =
            *reinterpret_cast<const float4*>(src + 4);
    }

    float o_acc[2][4] = {};
    float m_i[2] = {-1e30f, -1e30f};
    float l_i[2] = {0.f, 0.f};
    const float scale = 0.125f;   // 1/sqrt(64)
    const int r0 = ty * 2;
    const int c0 = tx * 2;
    const int cc0 = tx * 4;

    for (int s0 = 0; s0 < TT; s0 += BS) {
        {   // load K,V tiles
            int r = tid / 8;
            int c = (tid % 8) * 8;
            const float* ks = &Kg[(base + s0 + r) * CC + c];
            const float* vs = &Vg[(base + s0 + r) * CC + c];
            *reinterpret_cast<float4*>(&Ks[r][c]) =
                *reinterpret_cast<const float4*>(ks);
            *reinterpret_cast<float4*>(&Ks[r][c + 4]) =
                *reinterpret_cast<const float4*>(ks + 4);
            *reinterpret_cast<float4*>(&Vs[r][c]) =
                *reinterpret_cast<const float4*>(vs);
            *reinterpret_cast<float4*>(&Vs[r][c + 4]) =
                *reinterpret_cast<const float4*>(vs + 4);
        }
        __syncthreads();

        // S = Q K^T (2x2 per thread)
        float s_acc[2][2] = {};
#pragma unroll
        for (int k = 0; k < CC; k++) {
            float qa = Qs[r0][k], qb = Qs[r0 + 1][k];
            float ka = Ks[c0][k], kb = Ks[c0 + 1][k];
            s_acc[0][0] += qa * ka; s_acc[0][1] += qa * kb;
            s_acc[1][0] += qb * ka; s_acc[1][1] += qb * kb;
        }
        // mask + scale (mask is int32, nonzero = keep)
        float sv[2][2];
#pragma unroll
        for (int i = 0; i < 2; i++) {
            const int* mrow = &mask[(size_t)n * TT * TT +
                                    (size_t)(q0 + r0 + i) * TT + s0 + c0];
#pragma unroll
            for (int j = 0; j < 2; j++)
                sv[i][j] = mrow[j] ? s_acc[i][j] * scale : -1e30f;
        }
        // online softmax per row (16 lanes own each row)
#pragma unroll
        for (int i = 0; i < 2; i++) {
            float mx = fmaxf(sv[i][0], sv[i][1]);
#pragma unroll
            for (int o = 8; o > 0; o >>= 1)
                mx = fmaxf(mx, __shfl_xor_sync(0xffffffffu, mx, o, 16));
            float m_new = fmaxf(m_i[i], mx);
            float p0 = __expf(sv[i][0] - m_new);
            float p1 = __expf(sv[i][1] - m_new);
            float rs = p0 + p1;
#pragma unroll
            for (int o = 8; o > 0; o >>= 1)
                rs += __shfl_xor_sync(0xffffffffu, rs, o, 16);
            float alpha = __expf(m_i[i] - m_new);
            l_i[i] = l_i[i] * alpha + rs;
            m_i[i] = m_new;
#pragma unroll
            for (int j = 0; j < 4; j++) o_acc[i][j] *= alpha;
            Ps[r0 + i][c0] = p0;
            Ps[r0 + i][c0 + 1] = p1;
        }
        __syncthreads();

        // O += P @ V
#pragma unroll
        for (int s = 0; s < BS; s++) {
            float p0 = Ps[r0][s], p1 = Ps[r0 + 1][s];
            float v0 = Vs[s][cc0], v1 = Vs[s][cc0 + 1];
            float v2 = Vs[s][cc0 + 2], v3 = Vs[s][cc0 + 3];
            o_acc[0][0] += p0 * v0; o_acc[0][1] += p0 * v1;
            o_acc[0][2] += p0 * v2; o_acc[0][3] += p0 * v3;
            o_acc[1][0] += p1 * v0; o_acc[1][1] += p1 * v1;
            o_acc[1][2] += p1 * v2; o_acc[1][3] += p1 * v3;
        }
        __syncthreads();
    }

    // epilogue: normalize, write in [N, T, H*C] layout
#pragma unroll
    for (int i = 0; i < 2; i++) {
        float inv = 1.f / l_i[i];
        size_t o = ((size_t)n * TT + q0 + r0 + i) * DD + h * CC + cc0;
#pragma unroll
        for (int j = 0; j < 4; j++) g_o[o + j] = o_acc[i][j] * inv;
    }
}

// ---------------------------------------------------------------------------
extern "C" void kernel_launch(void* const* d_in, const int* in_sizes, int n_in,
                              void* d_out, int out_size) {
    const float* x = (const float*)d_in[0];
    const float* r = (const float*)d_in[1];
    const int* mask = (const int*)d_in[2];
    const float* Wqkv = (const float*)d_in[3];
    const float* Wout = (const float*)d_in[4];

    float* out = (float*)d_out;
    float* y = out;                                    // [N,T,D]
    float* kout = out + (size_t)NB * TT * DD;          // [N,H,T,C]
    float* vout = kout + (size_t)NB * HH * TT * CC;    // [N,H,T,C]

    float *qkv_p, *o_p;
    cudaGetSymbolAddress((void**)&qkv_p, g_qkv);
    cudaGetSymbolAddress((void**)&o_p, g_o);

    // 1) qkv = x @ W_qkv^T
    {
        dim3 g(3 * DD / 128, (NB * TT) / 128);
        gemm_tn<<<g, 256>>>(x, Wqkv, qkv_p, NB * TT, 3 * DD, DD);
    }
    // 2) RoPE + transpose (writes k,v outputs)
    {
        int tot = NB * TT * HH * (CC / 2);
        rope_kernel<<<(tot + 255) / 256, 256>>>(r, kout, vout);
    }
    // 3) attention -> g_o [N,T,D]
    {
        dim3 g(TT / 32, HH, NB);
        attn_kernel<<<g, 256>>>(kout, vout, mask);
    }
    // 4) y = o @ W_out^T
    {
        dim3 g(DD / 128, (NB * TT) / 128);
        gemm_tn<<<g, 256>>>(o_p, Wout, y, NB * TT, DD, DD);
    }
}

// round 3
// speedup vs baseline: 1.7195x; 1.7195x over previous
#include <cuda_runtime.h>
#include <math.h>

#define NB 4
#define TT 1024
#define DD 1024
#define HH 16
#define CC 64

// scratch
__device__ float g_qkv[(size_t)NB * TT * 3 * DD];       // [N*T, 3D]
__device__ float g_qT[(size_t)NB * HH * CC * TT];       // [n][h][c][t]
__device__ float g_kT[(size_t)NB * HH * CC * TT];       // [n][h][c][t]
__device__ float g_o[(size_t)NB * TT * DD];             // [N*T, D]
__device__ unsigned g_mbits[(size_t)NB * TT * TT / 32]; // packed mask

// ---------------------------------------------------------------------------
__device__ __forceinline__ unsigned f2tf(float x) {
    unsigned r;
    asm("cvt.rna.tf32.f32 %0, %1;" : "=r"(r) : "f"(x));
    return r;
}

__device__ __forceinline__ void mma_tf32(float c[4], const unsigned a[4],
                                         const unsigned b[2]) {
    asm volatile(
        "mma.sync.aligned.m16n8k8.row.col.f32.tf32.tf32.f32 "
        "{%0,%1,%2,%3},{%4,%5,%6,%7},{%8,%9},{%0,%1,%2,%3};"
        : "+f"(c[0]), "+f"(c[1]), "+f"(c[2]), "+f"(c[3])
        : "r"(a[0]), "r"(a[1]), "r"(a[2]), "r"(a[3]), "r"(b[0]), "r"(b[1]));
}

// ---------------------------------------------------------------------------
// tf32 tensor-core GEMM (TN): C[M,N] = A[M,K] @ B[N,K]^T, fp32 accumulate.
// BM=BN=128, BK=16, 256 threads / 8 warps (4m x 2n), warp tile 32x64.
// ---------------------------------------------------------------------------
__global__ __launch_bounds__(256) void gemm_tn_tf32(
    const float* __restrict__ A, const float* __restrict__ B,
    float* __restrict__ C, int M, int N, int K) {
    __shared__ unsigned As[128][20];
    __shared__ unsigned Bs[128][20];
    const int tid = threadIdx.x;
    const int m0 = blockIdx.y * 128, n0 = blockIdx.x * 128;
    const int warp = tid >> 5, lane = tid & 31;
    const int wm = (warp & 3) * 32, wn = (warp >> 2) * 64;
    const int g = lane >> 2, t = lane & 3;
    const int lrow = tid >> 1, lc = (tid & 1) * 8;

    float acc[2][8][4] = {};

    for (int k0 = 0; k0 < K; k0 += 16) {
        {
            const float* pa = &A[(size_t)(m0 + lrow) * K + k0 + lc];
            float4 v0 = *(const float4*)pa;
            float4 v1 = *(const float4*)(pa + 4);
            As[lrow][lc + 0] = f2tf(v0.x); As[lrow][lc + 1] = f2tf(v0.y);
            As[lrow][lc + 2] = f2tf(v0.z); As[lrow][lc + 3] = f2tf(v0.w);
            As[lrow][lc + 4] = f2tf(v1.x); As[lrow][lc + 5] = f2tf(v1.y);
            As[lrow][lc + 6] = f2tf(v1.z); As[lrow][lc + 7] = f2tf(v1.w);
            const float* pb = &B[(size_t)(n0 + lrow) * K + k0 + lc];
            float4 w0 = *(const float4*)pb;
            float4 w1 = *(const float4*)(pb + 4);
            Bs[lrow][lc + 0] = f2tf(w0.x); Bs[lrow][lc + 1] = f2tf(w0.y);
            Bs[lrow][lc + 2] = f2tf(w0.z); Bs[lrow][lc + 3] = f2tf(w0.w);
            Bs[lrow][lc + 4] = f2tf(w1.x); Bs[lrow][lc + 5] = f2tf(w1.y);
            Bs[lrow][lc + 6] = f2tf(w1.z); Bs[lrow][lc + 7] = f2tf(w1.w);
        }
        __syncthreads();
#pragma unroll
        for (int kk = 0; kk < 16; kk += 8) {
            unsigned a[2][4], b[8][2];
#pragma unroll
            for (int mi = 0; mi < 2; mi++) {
                int r = wm + mi * 16 + g;
                a[mi][0] = As[r][kk + t];
                a[mi][1] = As[r + 8][kk + t];
                a[mi][2] = As[r][kk + t + 4];
                a[mi][3] = As[r + 8][kk + t + 4];
            }
#pragma unroll
            for (int ni = 0; ni < 8; ni++) {
                int rb = wn + ni * 8 + g;
                b[ni][0] = Bs[rb][kk + t];
                b[ni][1] = Bs[rb][kk + t + 4];
            }
#pragma unroll
            for (int mi = 0; mi < 2; mi++)
#pragma unroll
                for (int ni = 0; ni < 8; ni++)
                    mma_tf32(acc[mi][ni], a[mi], b[ni]);
        }
        __syncthreads();
    }
#pragma unroll
    for (int mi = 0; mi < 2; mi++)
#pragma unroll
        for (int ni = 0; ni < 8; ni++) {
            int row = m0 + wm + mi * 16 + g;
            int col = n0 + wn + ni * 8 + 2 * t;
            float2 v01 = make_float2(acc[mi][ni][0], acc[mi][ni][1]);
            float2 v23 = make_float2(acc[mi][ni][2], acc[mi][ni][3]);
            *(float2*)&C[(size_t)row * N + col] = v01;
            *(float2*)&C[(size_t)(row + 8) * N + col] = v23;
        }
}

// ---------------------------------------------------------------------------
// Pack int32 bool mask -> bitmask.
// ---------------------------------------------------------------------------
__global__ void pack_mask(const int* __restrict__ mask,
                          unsigned* __restrict__ bits) {
    int i = blockIdx.x * blockDim.x + threadIdx.x;
    unsigned b = __ballot_sync(0xffffffffu, mask[i] != 0);
    if ((threadIdx.x & 31) == 0) bits[i >> 5] = b;
}

// ---------------------------------------------------------------------------
// RoPE + transposes. Writes q,k in k-major [n][h][c][t] for attention, plus
// k,v in [n][h][t][c] straight to the output buffer.
// ---------------------------------------------------------------------------
__global__ void rope_kernel(const float* __restrict__ r,
                            float* __restrict__ kout,
                            float* __restrict__ vout) {
    int idx = blockIdx.x * blockDim.x + threadIdx.x;
    const int TOT = NB * TT * HH * (CC / 2);
    if (idx >= TOT) return;
    int j = idx % (CC / 2);
    int h = (idx / (CC / 2)) % HH;
    int t = (idx / (CC / 2) / HH) % TT;
    int n = idx / (CC / 2) / HH / TT;
    size_t row = (size_t)n * TT + t;
    const float* p = &g_qkv[row * (3 * DD) + h * CC + 2 * j];
    float q0 = p[0], q1 = p[1];
    float k0 = p[DD], k1 = p[DD + 1];
    float v0 = p[2 * DD], v1 = p[2 * DD + 1];
    float ang = r[row * (CC / 2) + j];
    float cs = cosf(ang), sn = sinf(ang);
    float q0r = q0 * cs - q1 * sn, q1r = q0 * sn + q1 * cs;
    float k0r = k0 * cs - k1 * sn, k1r = k0 * sn + k1 * cs;
    size_t ot = ((size_t)(n * HH + h) * CC + 2 * j) * TT + t;   // [n][h][c][t]
    g_qT[ot] = q0r;       g_qT[ot + TT] = q1r;
    g_kT[ot] = k0r;       g_kT[ot + TT] = k1r;
    size_t oo = ((size_t)(n * HH + h) * TT + t) * CC + 2 * j;   // [n][h][t][c]
    kout[oo] = k0r; kout[oo + 1] = k1r;
    vout[oo] = v0;  vout[oo + 1] = v1;
}

// ---------------------------------------------------------------------------
// Flash attention, fp32 FMA. BQ=BS=64, 128 threads (16 tx x 8 ty),
// per-thread 8x4 S tile and 8x4 O tile. K-buffer reused for P.
// ---------------------------------------------------------------------------
__global__ __launch_bounds__(128) void attn_kernel(
    const float* __restrict__ qT, const float* __restrict__ kT,
    const float* __restrict__ V, const unsigned* __restrict__ mbits) {
    __shared__ float QsT[64 * 64];  // [k][qrow]
    __shared__ float KP[64 * 64];   // [k][srow] for S; then [qrow][s] = P
    __shared__ float Vs[64 * 64];   // [srow][c]

    const int n = blockIdx.z, h = blockIdx.y, q0 = blockIdx.x * 64;
    const int tid = threadIdx.x;
    const int tx = tid & 15, ty = tid >> 4;   // tx 0..15, ty 0..7
    const size_t hb = (size_t)(n * HH + h) * CC;       // qT/kT row base (c units)
    const size_t vb = (size_t)(n * HH + h) * TT;       // V row base (t units)

    {   // load Q tile (k-major: coalesced, conflict-free stores)
        int k = tid >> 1, ch = (tid & 1) * 32;
        const float* src = &qT[(hb + k) * TT + q0 + ch];
        float* dst = &QsT[k * 64 + ch];
#pragma unroll
        for (int u = 0; u < 8; u++)
            ((float4*)dst)[u] = ((const float4*)src)[u];
    }

    float o[8][4] = {};
    float mi[8], li[8];
#pragma unroll
    for (int i = 0; i < 8; i++) { mi[i] = -1e30f; li[i] = 0.f; }
    const float scale = 0.125f;   // 1/sqrt(64)

    for (int s0 = 0; s0 < TT; s0 += 64) {
        {   // load K (k-major) and V tiles
            int k = tid >> 1, ch = (tid & 1) * 32;
            const float* sk = &kT[(hb + k) * TT + s0 + ch];
            float* dk = &KP[k * 64 + ch];
#pragma unroll
            for (int u = 0; u < 8; u++)
                ((float4*)dk)[u] = ((const float4*)sk)[u];
            const float* sv = &V[(vb + s0 + k) * CC + ch];
            float* dv = &Vs[k * 64 + ch];
#pragma unroll
            for (int u = 0; u < 8; u++)
                ((float4*)dv)[u] = ((const float4*)sv)[u];
        }
        __syncthreads();

        // S = Q^T-major dot: s_[i][j] over k
        float s_[8][4] = {};
#pragma unroll
        for (int k = 0; k < 64; k++) {
            float4 k4 = *(float4*)&KP[k * 64 + tx * 4];
            float4 qa = *(float4*)&QsT[k * 64 + ty * 8];
            float4 qb = *(float4*)&QsT[k * 64 + ty * 8 + 4];
            s_[0][0] += qa.x * k4.x; s_[0][1] += qa.x * k4.y; s_[0][2] += qa.x * k4.z; s_[0][3] += qa.x * k4.w;
            s_[1][0] += qa.y * k4.x; s_[1][1] += qa.y * k4.y; s_[1][2] += qa.y * k4.z; s_[1][3] += qa.y * k4.w;
            s_[2][0] += qa.z * k4.x; s_[2][1] += qa.z * k4.y; s_[2][2] += qa.z * k4.z; s_[2][3] += qa.z * k4.w;
            s_[3][0] += qa.w * k4.x; s_[3][1] += qa.w * k4.y; s_[3][2] += qa.w * k4.z; s_[3][3] += qa.w * k4.w;
            s_[4][0] += qb.x * k4.x; s_[4][1] += qb.x * k4.y; s_[4][2] += qb.x * k4.z; s_[4][3] += qb.x * k4.w;
            s_[5][0] += qb.y * k4.x; s_[5][1] += qb.y * k4.y; s_[5][2] += qb.y * k4.z; s_[5][3] += qb.y * k4.w;
            s_[6][0] += qb.z * k4.x; s_[6][1] += qb.z * k4.y; s_[6][2] += qb.z * k4.z; s_[6][3] += qb.z * k4.w;
            s_[7][0] += qb.w * k4.x; s_[7][1] += qb.w * k4.y; s_[7][2] += qb.w * k4.z; s_[7][3] += qb.w * k4.w;
        }

        // mask + scale (in place)
#pragma unroll
        for (int i = 0; i < 8; i++) {
            int row = q0 + ty * 8 + i;
            unsigned w = mbits[((size_t)n * TT + row) * (TT / 32) +
                               (s0 >> 5) + (tx >> 3)];
#pragma unroll
            for (int j = 0; j < 4; j++)
                s_[i][j] = ((w >> ((tx * 4 + j) & 31)) & 1u)
                               ? s_[i][j] * scale : -1e30f;
        }

        // online softmax (rows split over 16 tx lanes)
#pragma unroll
        for (int i = 0; i < 8; i++) {
            float mx = fmaxf(fmaxf(s_[i][0], s_[i][1]),
                             fmaxf(s_[i][2], s_[i][3]));
#pragma unroll
            for (int off = 8; off > 0; off >>= 1)
                mx = fmaxf(mx, __shfl_xor_sync(0xffffffffu, mx, off, 16));
            float mn = fmaxf(mi[i], mx);
            float rs = 0.f;
#pragma unroll
            for (int j = 0; j < 4; j++) {
                s_[i][j] = __expf(s_[i][j] - mn);
                rs += s_[i][j];
            }
#pragma unroll
            for (int off = 8; off > 0; off >>= 1)
                rs += __shfl_xor_sync(0xffffffffu, rs, off, 16);
            float al = __expf(mi[i] - mn);
            li[i] = li[i] * al + rs;
            mi[i] = mn;
#pragma unroll
            for (int j = 0; j < 4; j++) o[i][j] *= al;
        }
        __syncthreads();   // all S reads of KP done

        // write P into KP as [qrow][s]
#pragma unroll
        for (int i = 0; i < 8; i++)
            *(float4*)&KP[(ty * 8 + i) * 64 + tx * 4] =
                make_float4(s_[i][0], s_[i][1], s_[i][2], s_[i][3]);
        __syncthreads();

        // O += P @ V
#pragma unroll
        for (int s = 0; s < 64; s += 4) {
            float4 v0 = *(float4*)&Vs[(s + 0) * 64 + tx * 4];
            float4 v1 = *(float4*)&Vs[(s + 1) * 64 + tx * 4];
            float4 v2 = *(float4*)&Vs[(s + 2) * 64 + tx * 4];
            float4 v3 = *(float4*)&Vs[(s + 3) * 64 + tx * 4];
#pragma unroll
            for (int i = 0; i < 8; i++) {
                float4 p4 = *(float4*)&KP[(ty * 8 + i) * 64 + s];
                o[i][0] += p4.x * v0.x + p4.y * v1.x + p4.z * v2.x + p4.w * v3.x;
                o[i][1] += p4.x * v0.y + p4.y * v1.y + p4.z * v2.y + p4.w * v3.y;
                o[i][2] += p4.x * v0.z + p4.y * v1.z + p4.z * v2.z + p4.w * v3.z;
                o[i][3] += p4.x * v0.w + p4.y * v1.w + p4.z * v2.w + p4.w * v3.w;
            }
        }
        __syncthreads();
    }

    // epilogue: write O in [N, T, H*C]
#pragma unroll
    for (int i = 0; i < 8; i++) {
        float inv = 1.f / li[i];
        size_t oo = ((size_t)n * TT + q0 + ty * 8 + i) * DD + h * CC + tx * 4;
        *(float4*)&g_o[oo] = make_float4(o[i][0] * inv, o[i][1] * inv,
                                         o[i][2] * inv, o[i][3] * inv);
    }
}

// ---------------------------------------------------------------------------
extern "C" void kernel_launch(void* const* d_in, const int* in_sizes, int n_in,
                              void* d_out, int out_size) {
    const float* x = (const float*)d_in[0];
    const float* r = (const float*)d_in[1];
    const int* mask = (const int*)d_in[2];
    const float* Wqkv = (const float*)d_in[3];
    const float* Wout = (const float*)d_in[4];

    float* out = (float*)d_out;
    float* y = out;                                    // [N,T,D]
    float* kout = out + (size_t)NB * TT * DD;          // [N,H,T,C]
    float* vout = kout + (size_t)NB * HH * TT * CC;    // [N,H,T,C]

    float *qkv_p, *o_p, *qT_p, *kT_p;
    unsigned* mb_p;
    cudaGetSymbolAddress((void**)&qkv_p, g_qkv);
    cudaGetSymbolAddress((void**)&o_p, g_o);
    cudaGetSymbolAddress((void**)&qT_p, g_qT);
    cudaGetSymbolAddress((void**)&kT_p, g_kT);
    cudaGetSymbolAddress((void**)&mb_p, g_mbits);

    // 1) qkv = x @ W_qkv^T  (tf32 tensor cores)
    {
        dim3 g(3 * DD / 128, (NB * TT) / 128);
        gemm_tn_tf32<<<g, 256>>>(x, Wqkv, qkv_p, NB * TT, 3 * DD, DD);
    }
    // 2) pack mask to bits
    pack_mask<<<(NB * TT * TT) / 256, 256>>>(mask, mb_p);
    // 3) RoPE + transposes (writes k,v outputs)
    {
        int tot = NB * TT * HH * (CC / 2);
        rope_kernel<<<(tot + 255) / 256, 256>>>(r, kout, vout);
    }
    // 4) attention -> g_o [N,T,D]
    {
        dim3 g(TT / 64, HH, NB);
        attn_kernel<<<g, 128>>>(qT_p, kT_p, vout, mb_p);
    }
    // 5) y = o @ W_out^T  (tf32 tensor cores)
    {
        dim3 g(DD / 128, (NB * TT) / 128);
        gemm_tn_tf32<<<g, 256>>>(o_p, Wout, y, NB * TT, DD, DD);
    }
}

// round 4
// speedup vs baseline: 3.1837x; 1.8515x over previous
#include <cuda_runtime.h>
#include <math.h>

#define NB 4
#define TT 1024
#define DD 1024
#define HH 16
#define CC 64

// scratch
__device__ float g_qkv[(size_t)NB * TT * 3 * DD];       // [N*T, 3D]
__device__ float g_q[(size_t)NB * HH * TT * CC];        // rotated q [n,h,t,c]
__device__ float g_o[(size_t)NB * TT * DD];             // [N*T, D]
__device__ unsigned g_mbits[(size_t)NB * TT * TT / 32]; // packed mask

// ---------------------------------------------------------------------------
__device__ __forceinline__ unsigned f2tf(float x) {
    unsigned r;
    asm("cvt.rna.tf32.f32 %0, %1;" : "=r"(r) : "f"(x));
    return r;
}

__device__ __forceinline__ void mma_tf32(float c[4], const unsigned a[4],
                                         const unsigned b[2]) {
    asm volatile(
        "mma.sync.aligned.m16n8k8.row.col.f32.tf32.tf32.f32 "
        "{%0,%1,%2,%3},{%4,%5,%6,%7},{%8,%9},{%0,%1,%2,%3};"
        : "+f"(c[0]), "+f"(c[1]), "+f"(c[2]), "+f"(c[3])
        : "r"(a[0]), "r"(a[1]), "r"(a[2]), "r"(a[3]), "r"(b[0]), "r"(b[1]));
}

// ---------------------------------------------------------------------------
// tf32 tensor-core GEMM (TN): C[M,N] = A[M,K] @ B[N,K]^T, fp32 accumulate.
// ---------------------------------------------------------------------------
__global__ __launch_bounds__(256) void gemm_tn_tf32(
    const float* __restrict__ A, const float* __restrict__ B,
    float* __restrict__ C, int M, int N, int K) {
    __shared__ unsigned As[128][20];
    __shared__ unsigned Bs[128][20];
    const int tid = threadIdx.x;
    const int m0 = blockIdx.y * 128, n0 = blockIdx.x * 128;
    const int warp = tid >> 5, lane = tid & 31;
    const int wm = (warp & 3) * 32, wn = (warp >> 2) * 64;
    const int g = lane >> 2, t = lane & 3;
    const int lrow = tid >> 1, lc = (tid & 1) * 8;

    float acc[2][8][4] = {};

    for (int k0 = 0; k0 < K; k0 += 16) {
        {
            const float* pa = &A[(size_t)(m0 + lrow) * K + k0 + lc];
            float4 v0 = *(const float4*)pa;
            float4 v1 = *(const float4*)(pa + 4);
            As[lrow][lc + 0] = f2tf(v0.x); As[lrow][lc + 1] = f2tf(v0.y);
            As[lrow][lc + 2] = f2tf(v0.z); As[lrow][lc + 3] = f2tf(v0.w);
            As[lrow][lc + 4] = f2tf(v1.x); As[lrow][lc + 5] = f2tf(v1.y);
            As[lrow][lc + 6] = f2tf(v1.z); As[lrow][lc + 7] = f2tf(v1.w);
            const float* pb = &B[(size_t)(n0 + lrow) * K + k0 + lc];
            float4 w0 = *(const float4*)pb;
            float4 w1 = *(const float4*)(pb + 4);
            Bs[lrow][lc + 0] = f2tf(w0.x); Bs[lrow][lc + 1] = f2tf(w0.y);
            Bs[lrow][lc + 2] = f2tf(w0.z); Bs[lrow][lc + 3] = f2tf(w0.w);
            Bs[lrow][lc + 4] = f2tf(w1.x); Bs[lrow][lc + 5] = f2tf(w1.y);
            Bs[lrow][lc + 6] = f2tf(w1.z); Bs[lrow][lc + 7] = f2tf(w1.w);
        }
        __syncthreads();
#pragma unroll
        for (int kk = 0; kk < 16; kk += 8) {
            unsigned a[2][4], b[8][2];
#pragma unroll
            for (int mi = 0; mi < 2; mi++) {
                int r = wm + mi * 16 + g;
                a[mi][0] = As[r][kk + t];
                a[mi][1] = As[r + 8][kk + t];
                a[mi][2] = As[r][kk + t + 4];
                a[mi][3] = As[r + 8][kk + t + 4];
            }
#pragma unroll
            for (int ni = 0; ni < 8; ni++) {
                int rb = wn + ni * 8 + g;
                b[ni][0] = Bs[rb][kk + t];
                b[ni][1] = Bs[rb][kk + t + 4];
            }
#pragma unroll
            for (int mi = 0; mi < 2; mi++)
#pragma unroll
                for (int ni = 0; ni < 8; ni++)
                    mma_tf32(acc[mi][ni], a[mi], b[ni]);
        }
        __syncthreads();
    }
#pragma unroll
    for (int mi = 0; mi < 2; mi++)
#pragma unroll
        for (int ni = 0; ni < 8; ni++) {
            int row = m0 + wm + mi * 16 + g;
            int col = n0 + wn + ni * 8 + 2 * t;
            float2 v01 = make_float2(acc[mi][ni][0], acc[mi][ni][1]);
            float2 v23 = make_float2(acc[mi][ni][2], acc[mi][ni][3]);
            *(float2*)&C[(size_t)row * N + col] = v01;
            *(float2*)&C[(size_t)(row + 8) * N + col] = v23;
        }
}

// ---------------------------------------------------------------------------
__global__ void pack_mask(const int* __restrict__ mask,
                          unsigned* __restrict__ bits) {
    int i = blockIdx.x * blockDim.x + threadIdx.x;
    unsigned b = __ballot_sync(0xffffffffu, mask[i] != 0);
    if ((threadIdx.x & 31) == 0) bits[i >> 5] = b;
}

// ---------------------------------------------------------------------------
// RoPE + transpose: q -> g_q [n,h,t,c]; k,v -> output buffer [n,h,t,c].
// ---------------------------------------------------------------------------
__global__ void rope_kernel(const float* __restrict__ r,
                            float* __restrict__ kout,
                            float* __restrict__ vout) {
    int idx = blockIdx.x * blockDim.x + threadIdx.x;
    const int TOT = NB * TT * HH * (CC / 2);
    if (idx >= TOT) return;
    int j = idx % (CC / 2);
    int h = (idx / (CC / 2)) % HH;
    int t = (idx / (CC / 2) / HH) % TT;
    int n = idx / (CC / 2) / HH / TT;
    size_t row = (size_t)n * TT + t;
    const float* p = &g_qkv[row * (3 * DD) + h * CC + 2 * j];
    float q0 = p[0], q1 = p[1];
    float k0 = p[DD], k1 = p[DD + 1];
    float v0 = p[2 * DD], v1 = p[2 * DD + 1];
    float ang = r[row * (CC / 2) + j];
    float cs = cosf(ang), sn = sinf(ang);
    size_t oo = ((size_t)(n * HH + h) * TT + t) * CC + 2 * j;
    g_q[oo] = q0 * cs - q1 * sn;
    g_q[oo + 1] = q0 * sn + q1 * cs;
    kout[oo] = k0 * cs - k1 * sn;
    kout[oo + 1] = k0 * sn + k1 * cs;
    vout[oo] = v0;
    vout[oo + 1] = v1;
}

// ---------------------------------------------------------------------------
// Flash attention with tf32 mma. BQ=128, BS=64, 256 threads / 8 warps.
// Warp w owns q-rows [w*16, w*16+16). P tile is warp-private.
// Smem (dynamic, stride 68 words for conflict-free fragment loads):
//   Qs[128][68] | Ks[64][68] | Vt[64][68] (c-major) | Ps[128][68]
// ---------------------------------------------------------------------------
#define AT_STRIDE 68
#define SM_QS 0
#define SM_KS (128 * AT_STRIDE)
#define SM_VT (SM_KS + 64 * AT_STRIDE)
#define SM_PS (SM_VT + 64 * AT_STRIDE)
#define AT_SMEM_WORDS (SM_PS + 128 * AT_STRIDE)

__global__ __launch_bounds__(256, 2) void attn_mma(
    const float* __restrict__ Q, const float* __restrict__ Kg,
    const float* __restrict__ Vg, const unsigned* __restrict__ mbits) {
    extern __shared__ unsigned sm[];
    unsigned* Qs = sm + SM_QS;
    unsigned* Ks = sm + SM_KS;
    unsigned* Vt = sm + SM_VT;
    unsigned* Ps = sm + SM_PS;

    const int n = blockIdx.z, h = blockIdx.y, q0 = blockIdx.x * 128;
    const int tid = threadIdx.x;
    const int warp = tid >> 5, lane = tid & 31;
    const int g = lane >> 2, t = lane & 3;
    const int wq = warp * 16;
    const size_t base = (size_t)(n * HH + h) * TT;
    const float scale = 0.125f;   // 1/sqrt(64), exact power of 2

    {   // load Q tile (scale folded into conversion)
        int qr = tid >> 1, qc = (tid & 1) * 32;
        const float* src = &Q[(base + q0 + qr) * CC + qc];
        unsigned* dst = &Qs[qr * AT_STRIDE + qc];
#pragma unroll
        for (int u = 0; u < 8; u++) {
            float4 v = ((const float4*)src)[u];
            dst[4 * u + 0] = f2tf(v.x * scale);
            dst[4 * u + 1] = f2tf(v.y * scale);
            dst[4 * u + 2] = f2tf(v.z * scale);
            dst[4 * u + 3] = f2tf(v.w * scale);
        }
    }

    float o[8][4] = {};
    float mi0 = -1e30f, mi1 = -1e30f, li0 = 0.f, li1 = 0.f;
    const int row0 = q0 + wq + g, row1 = row0 + 8;

    for (int s0 = 0; s0 < TT; s0 += 64) {
        __syncthreads();   // prior-iter smem reads done
        {   // load K row-major, V transposed (c-major)
            int kr = tid >> 2, kc = (tid & 3) * 16;
            const float* ks = &Kg[(base + s0 + kr) * CC + kc];
            const float* vs = &Vg[(base + s0 + kr) * CC + kc];
#pragma unroll
            for (int u = 0; u < 4; u++) {
                float4 a = ((const float4*)ks)[u];
                unsigned* dk = &Ks[kr * AT_STRIDE + kc + 4 * u];
                dk[0] = f2tf(a.x); dk[1] = f2tf(a.y);
                dk[2] = f2tf(a.z); dk[3] = f2tf(a.w);
                float4 b = ((const float4*)vs)[u];
                int c = kc + 4 * u;
                Vt[(c + 0) * AT_STRIDE + kr] = f2tf(b.x);
                Vt[(c + 1) * AT_STRIDE + kr] = f2tf(b.y);
                Vt[(c + 2) * AT_STRIDE + kr] = f2tf(b.z);
                Vt[(c + 3) * AT_STRIDE + kr] = f2tf(b.w);
            }
        }
        __syncthreads();

        // ---- S = (Q*scale) K^T -----------------------------------------
        float s_[8][4] = {};
#pragma unroll
        for (int kk = 0; kk < CC; kk += 8) {
            unsigned a[4];
            a[0] = Qs[(wq + g) * AT_STRIDE + kk + t];
            a[1] = Qs[(wq + g + 8) * AT_STRIDE + kk + t];
            a[2] = Qs[(wq + g) * AT_STRIDE + kk + t + 4];
            a[3] = Qs[(wq + g + 8) * AT_STRIDE + kk + t + 4];
#pragma unroll
            for (int j = 0; j < 8; j++) {
                unsigned b[2];
                b[0] = Ks[(j * 8 + g) * AT_STRIDE + kk + t];
                b[1] = Ks[(j * 8 + g) * AT_STRIDE + kk + t + 4];
                mma_tf32(s_[j], a, b);
            }
        }

        // ---- mask -------------------------------------------------------
        {
            const unsigned* mr0 =
                &mbits[((size_t)n * TT + row0) * (TT / 32) + (s0 >> 5)];
            const unsigned* mr1 =
                &mbits[((size_t)n * TT + row1) * (TT / 32) + (s0 >> 5)];
            unsigned w00 = mr0[0], w01 = mr0[1];
            unsigned w10 = mr1[0], w11 = mr1[1];
#pragma unroll
            for (int j = 0; j < 8; j++) {
                int c = j * 8 + 2 * t;
                unsigned wa0 = (c < 32) ? w00 : w01;
                unsigned wa1 = (c < 32) ? w10 : w11;
                int b0 = (wa0 >> (c & 31)) & 1, b1 = (wa0 >> ((c + 1) & 31)) & 1;
                int b2 = (wa1 >> (c & 31)) & 1, b3 = (wa1 >> ((c + 1) & 31)) & 1;
                if (!b0) s_[j][0] = -1e30f;
                if (!b1) s_[j][1] = -1e30f;
                if (!b2) s_[j][2] = -1e30f;
                if (!b3) s_[j][3] = -1e30f;
            }
        }

        // ---- online softmax (rows g and g+8, 4 lanes t share a row) ----
        float mx0 = -1e30f, mx1 = -1e30f;
#pragma unroll
        for (int j = 0; j < 8; j++) {
            mx0 = fmaxf(mx0, fmaxf(s_[j][0], s_[j][1]));
            mx1 = fmaxf(mx1, fmaxf(s_[j][2], s_[j][3]));
        }
        mx0 = fmaxf(mx0, __shfl_xor_sync(0xffffffffu, mx0, 1));
        mx0 = fmaxf(mx0, __shfl_xor_sync(0xffffffffu, mx0, 2));
        mx1 = fmaxf(mx1, __shfl_xor_sync(0xffffffffu, mx1, 1));
        mx1 = fmaxf(mx1, __shfl_xor_sync(0xffffffffu, mx1, 2));
        float mn0 = fmaxf(mi0, mx0), mn1 = fmaxf(mi1, mx1);
        float rs0 = 0.f, rs1 = 0.f;
#pragma unroll
        for (int j = 0; j < 8; j++) {
            s_[j][0] = __expf(s_[j][0] - mn0);
            s_[j][1] = __expf(s_[j][1] - mn0);
            s_[j][2] = __expf(s_[j][2] - mn1);
            s_[j][3] = __expf(s_[j][3] - mn1);
            rs0 += s_[j][0] + s_[j][1];
            rs1 += s_[j][2] + s_[j][3];
        }
        rs0 += __shfl_xor_sync(0xffffffffu, rs0, 1);
        rs0 += __shfl_xor_sync(0xffffffffu, rs0, 2);
        rs1 += __shfl_xor_sync(0xffffffffu, rs1, 1);
        rs1 += __shfl_xor_sync(0xffffffffu, rs1, 2);
        float al0 = __expf(mi0 - mn0), al1 = __expf(mi1 - mn1);
        li0 = li0 * al0 + rs0;
        li1 = li1 * al1 + rs1;
        mi0 = mn0; mi1 = mn1;
#pragma unroll
        for (int j = 0; j < 8; j++) {
            o[j][0] *= al0; o[j][1] *= al0;
            o[j][2] *= al1; o[j][3] *= al1;
        }

        // ---- P -> smem (warp-private rows) ------------------------------
#pragma unroll
        for (int j = 0; j < 8; j++) {
            int c = j * 8 + 2 * t;
            Ps[(wq + g) * AT_STRIDE + c] = f2tf(s_[j][0]);
            Ps[(wq + g) * AT_STRIDE + c + 1] = f2tf(s_[j][1]);
            Ps[(wq + g + 8) * AT_STRIDE + c] = f2tf(s_[j][2]);
            Ps[(wq + g + 8) * AT_STRIDE + c + 1] = f2tf(s_[j][3]);
        }
        __syncwarp();

        // ---- O += P V ---------------------------------------------------
#pragma unroll
        for (int kk = 0; kk < 64; kk += 8) {
            unsigned a[4];
            a[0] = Ps[(wq + g) * AT_STRIDE + kk + t];
            a[1] = Ps[(wq + g + 8) * AT_STRIDE + kk + t];
            a[2] = Ps[(wq + g) * AT_STRIDE + kk + t + 4];
            a[3] = Ps[(wq + g + 8) * AT_STRIDE + kk + t + 4];
#pragma unroll
            for (int j = 0; j < 8; j++) {
                unsigned b[2];
                b[0] = Vt[(j * 8 + g) * AT_STRIDE + kk + t];
                b[1] = Vt[(j * 8 + g) * AT_STRIDE + kk + t + 4];
                mma_tf32(o[j], a, b);
            }
        }
    }

    // epilogue: normalize, write to g_o [N,T,D]
    float inv0 = 1.f / li0, inv1 = 1.f / li1;
#pragma unroll
    for (int j = 0; j < 8; j++) {
        int c = h * CC + j * 8 + 2 * t;
        *(float2*)&g_o[((size_t)n * TT + row0) * DD + c] =
            make_float2(o[j][0] * inv0, o[j][1] * inv0);
        *(float2*)&g_o[((size_t)n * TT + row1) * DD + c] =
            make_float2(o[j][2] * inv1, o[j][3] * inv1);
    }
}

// ---------------------------------------------------------------------------
extern "C" void kernel_launch(void* const* d_in, const int* in_sizes, int n_in,
                              void* d_out, int out_size) {
    const float* x = (const float*)d_in[0];
    const float* r = (const float*)d_in[1];
    const int* mask = (const int*)d_in[2];
    const float* Wqkv = (const float*)d_in[3];
    const float* Wout = (const float*)d_in[4];

    float* out = (float*)d_out;
    float* y = out;                                    // [N,T,D]
    float* kout = out + (size_t)NB * TT * DD;          // [N,H,T,C]
    float* vout = kout + (size_t)NB * HH * TT * CC;    // [N,H,T,C]

    float *qkv_p, *o_p, *q_p;
    unsigned* mb_p;
    cudaGetSymbolAddress((void**)&qkv_p, g_qkv);
    cudaGetSymbolAddress((void**)&o_p, g_o);
    cudaGetSymbolAddress((void**)&q_p, g_q);
    cudaGetSymbolAddress((void**)&mb_p, g_mbits);

    static int attr_set = 0;
    if (!attr_set) {
        cudaFuncSetAttribute(attn_mma,
                             cudaFuncAttributeMaxDynamicSharedMemorySize,
                             AT_SMEM_WORDS * 4);
        attr_set = 1;
    }

    // 1) qkv = x @ W_qkv^T
    {
        dim3 g(3 * DD / 128, (NB * TT) / 128);
        gemm_tn_tf32<<<g, 256>>>(x, Wqkv, qkv_p, NB * TT, 3 * DD, DD);
    }
    // 2) pack mask
    pack_mask<<<(NB * TT * TT) / 256, 256>>>(mask, mb_p);
    // 3) RoPE (writes k,v outputs + g_q)
    {
        int tot = NB * TT * HH * (CC / 2);
        rope_kernel<<<(tot + 255) / 256, 256>>>(r, kout, vout);
    }
    // 4) attention -> g_o [N,T,D]
    {
        dim3 g(TT / 128, HH, NB);
        attn_mma<<<g, 256, AT_SMEM_WORDS * 4>>>(q_p, kout, vout, mb_p);
    }
    // 5) y = o @ W_out^T
    {
        dim3 g(DD / 128, (NB * TT) / 128);
        gemm_tn_tf32<<<g, 256>>>(o_p, Wout, y, NB * TT, DD, DD);
    }
}